// round 1
// baseline (speedup 1.0000x reference)
#include <cuda_runtime.h>
#include <math.h>

#define BB 2
#define NN 2048
#define CC 1024
#define HH 16
#define DD 64
#define FF 4096
#define RR (BB*NN)   // 4096 rows

// ---------------- scratch (static device allocations; allowed) ----------------
__device__ float g_xn [(size_t)RR*CC];
__device__ float g_q  [(size_t)RR*CC];
__device__ float g_k  [(size_t)RR*CC];
__device__ float g_v  [(size_t)RR*CC];
__device__ float g_S  [(size_t)BB*HH*NN*NN];   // 536 MB scores
__device__ float g_y  [(size_t)RR*CC];
__device__ float g_x2 [(size_t)RR*CC];
__device__ float g_hb [(size_t)RR*FF];

// ---------------- layernorm ----------------
__global__ void layernorm_kernel(const float* __restrict__ x,
                                 const float* __restrict__ gamma,
                                 const float* __restrict__ beta,
                                 float* __restrict__ out, int C) {
    __shared__ float red[256];
    int row = blockIdx.x;
    const float* xr = x + (size_t)row * C;
    float* orow = out + (size_t)row * C;
    int t = threadIdx.x;

    float s = 0.f;
    for (int i = t; i < C; i += 256) s += xr[i];
    red[t] = s; __syncthreads();
    for (int st = 128; st > 0; st >>= 1) { if (t < st) red[t] += red[t + st]; __syncthreads(); }
    float mu = red[0] / (float)C;
    __syncthreads();

    float v = 0.f;
    for (int i = t; i < C; i += 256) { float d = xr[i] - mu; v += d * d; }
    red[t] = v; __syncthreads();
    for (int st = 128; st > 0; st >>= 1) { if (t < st) red[t] += red[t + st]; __syncthreads(); }
    float inv = rsqrtf(red[0] / (float)C + 1e-6f);

    for (int i = t; i < C; i += 256)
        orow[i] = (xr[i] - mu) * inv * gamma[i] + beta[i];
}

// ---------------- softmax over rows ----------------
__global__ void softmax_kernel(float* __restrict__ S, int n) {
    __shared__ float red[256];
    size_t row = blockIdx.x;
    float* r = S + row * (size_t)n;
    int t = threadIdx.x;

    float mx = -1e30f;
    for (int i = t; i < n; i += 256) mx = fmaxf(mx, r[i]);
    red[t] = mx; __syncthreads();
    for (int st = 128; st > 0; st >>= 1) { if (t < st) red[t] = fmaxf(red[t], red[t + st]); __syncthreads(); }
    mx = red[0]; __syncthreads();

    float s = 0.f;
    for (int i = t; i < n; i += 256) { float e = expf(r[i] - mx); r[i] = e; s += e; }
    red[t] = s; __syncthreads();
    for (int st = 128; st > 0; st >>= 1) { if (t < st) red[t] += red[t + st]; __syncthreads(); }
    float invs = 1.f / red[0];

    for (int i = t; i < n; i += 256) r[i] *= invs;
}

// ---------------- generic batched SGEMM ----------------
// C[m,n] = epi( alpha * sum_k A[m,k] * B(k,n | n,k) + bias[n] (+resid[m,n]) )
// batch: z in grid.z; zb=z/nh, zh=z%nh; each operand offset zb*off_b + zh*off_h.
template<bool TRANSB, bool GELU>
__global__ void sgemm_kernel(int M, int N, int K,
                             const float* __restrict__ A, int lda, long offA_b, long offA_h,
                             const float* __restrict__ Bm, int ldb, long offB_b, long offB_h,
                             float* __restrict__ C, int ldc, long offC_b, long offC_h,
                             float alpha,
                             const float* __restrict__ bias,
                             const float* __restrict__ resid, int ldr, long offR_b, long offR_h,
                             int nh) {
    const int BM = 128, BN = 128, BK = 8, TM = 8, TN = 8;
    int z = blockIdx.z;
    int zb = z / nh, zh = z % nh;
    A  += (long)zb * offA_b + (long)zh * offA_h;
    Bm += (long)zb * offB_b + (long)zh * offB_h;
    C  += (long)zb * offC_b + (long)zh * offC_h;
    if (resid) resid += (long)zb * offR_b + (long)zh * offR_h;

    __shared__ float As[BK][BM];
    __shared__ float Bs[BK][BN];

    int tid = threadIdx.x;              // 256
    int tx = tid % (BN / TN);           // 0..15
    int ty = tid / (BN / TN);           // 0..15
    int row0 = blockIdx.y * BM;
    int col0 = blockIdx.x * BN;

    float acc[TM][TN];
    #pragma unroll
    for (int i = 0; i < TM; i++)
        #pragma unroll
        for (int j = 0; j < TN; j++) acc[i][j] = 0.f;

    for (int k0 = 0; k0 < K; k0 += BK) {
        // A tile: BM x BK
        for (int idx = tid; idx < BM * BK; idx += 256) {
            int m = idx / BK, kk = idx % BK;
            int gr = row0 + m, gc = k0 + kk;
            As[kk][m] = (gr < M && gc < K) ? A[(long)gr * lda + gc] : 0.f;
        }
        // B tile: BK x BN
        if (!TRANSB) {
            for (int idx = tid; idx < BK * BN; idx += 256) {
                int kk = idx / BN, n = idx % BN;
                int gr = k0 + kk, gc = col0 + n;
                Bs[kk][n] = (gr < K && gc < N) ? Bm[(long)gr * ldb + gc] : 0.f;
            }
        } else {
            for (int idx = tid; idx < BK * BN; idx += 256) {
                int n = idx / BK, kk = idx % BK;
                int gr = col0 + n, gc = k0 + kk;
                Bs[kk][n] = (gr < N && gc < K) ? Bm[(long)gr * ldb + gc] : 0.f;
            }
        }
        __syncthreads();

        #pragma unroll
        for (int kk = 0; kk < BK; kk++) {
            float a[TM], b[TN];
            #pragma unroll
            for (int i = 0; i < TM; i++) a[i] = As[kk][ty * TM + i];
            #pragma unroll
            for (int j = 0; j < TN; j++) b[j] = Bs[kk][tx * TN + j];
            #pragma unroll
            for (int i = 0; i < TM; i++)
                #pragma unroll
                for (int j = 0; j < TN; j++) acc[i][j] = fmaf(a[i], b[j], acc[i][j]);
        }
        __syncthreads();
    }

    #pragma unroll
    for (int i = 0; i < TM; i++) {
        int gr = row0 + ty * TM + i;
        if (gr >= M) continue;
        #pragma unroll
        for (int j = 0; j < TN; j++) {
            int gc = col0 + tx * TN + j;
            if (gc >= N) continue;
            float v = acc[i][j] * alpha;
            if (bias) v += bias[gc];
            if (GELU) v = 0.5f * v * (1.f + erff(v * 0.70710678118654752f));
            if (resid) v += resid[(long)gr * ldr + gc];
            C[(long)gr * ldc + gc] = v;
        }
    }
}

// ---------------- host ----------------
static float* sym_addr(const void* s) {
    void* p = nullptr;
    cudaGetSymbolAddress(&p, s);
    return (float*)p;
}

extern "C" void kernel_launch(void* const* d_in, const int* in_sizes, int n_in,
                              void* d_out, int out_size) {
    const float* x      = (const float*)d_in[0];
    const float* Wq     = (const float*)d_in[1];
    const float* Wk     = (const float*)d_in[2];
    const float* Wv     = (const float*)d_in[3];
    const float* Wp     = (const float*)d_in[4];
    const float* bp     = (const float*)d_in[5];
    const float* W1     = (const float*)d_in[6];
    const float* b1     = (const float*)d_in[7];
    const float* W2     = (const float*)d_in[8];
    const float* b2     = (const float*)d_in[9];
    const float* gamma1 = (const float*)d_in[10];
    const float* beta1  = (const float*)d_in[11];
    const float* gamma2 = (const float*)d_in[12];
    const float* beta2  = (const float*)d_in[13];
    float* out = (float*)d_out;

    float* xn = sym_addr(g_xn);
    float* q  = sym_addr(g_q);
    float* k  = sym_addr(g_k);
    float* v  = sym_addr(g_v);
    float* S  = sym_addr(g_S);
    float* y  = sym_addr(g_y);
    float* x2 = sym_addr(g_x2);
    float* hb = sym_addr(g_hb);

    const float scale = 0.125f; // 64^-0.5

    // 1. LN1
    layernorm_kernel<<<RR, 256>>>(x, gamma1, beta1, xn, CC);

    // 2-4. QKV projections
    {
        dim3 grid(CC / 128, RR / 128, 1);
        sgemm_kernel<false, false><<<grid, 256>>>(RR, CC, CC,
            xn, CC, 0, 0, Wq, CC, 0, 0, q, CC, 0, 0,
            scale, nullptr, nullptr, 0, 0, 0, 1);
        sgemm_kernel<false, false><<<grid, 256>>>(RR, CC, CC,
            xn, CC, 0, 0, Wk, CC, 0, 0, k, CC, 0, 0,
            1.f, nullptr, nullptr, 0, 0, 0, 1);
        sgemm_kernel<false, false><<<grid, 256>>>(RR, CC, CC,
            xn, CC, 0, 0, Wv, CC, 0, 0, v, CC, 0, 0,
            1.f, nullptr, nullptr, 0, 0, 0, 1);
    }

    // 5. scores: per (b,h): S = q_bh @ k_bh^T    [NN x NN], K = DD
    {
        dim3 grid(NN / 128, NN / 128, BB * HH);
        sgemm_kernel<true, false><<<grid, 256>>>(NN, NN, DD,
            q, CC, (long)NN * CC, DD,
            k, CC, (long)NN * CC, DD,
            S, NN, (long)HH * NN * NN, (long)NN * NN,
            1.f, nullptr, nullptr, 0, 0, 0, HH);
    }

    // 6. softmax rows
    softmax_kernel<<<BB * HH * NN, 256>>>(S, NN);

    // 7. y_bh = P @ v_bh   [NN x DD], K = NN
    {
        dim3 grid(1, NN / 128, BB * HH);
        sgemm_kernel<false, false><<<grid, 256>>>(NN, DD, NN,
            S, NN, (long)HH * NN * NN, (long)NN * NN,
            v, CC, (long)NN * CC, DD,
            y, CC, (long)NN * CC, DD,
            1.f, nullptr, nullptr, 0, 0, 0, HH);
    }

    // 8. x2 = x + y @ Wp + bp
    {
        dim3 grid(CC / 128, RR / 128, 1);
        sgemm_kernel<false, false><<<grid, 256>>>(RR, CC, CC,
            y, CC, 0, 0, Wp, CC, 0, 0, x2, CC, 0, 0,
            1.f, bp, x, CC, 0, 0, 1);
    }

    // 9. LN2 (reuse xn buffer)
    layernorm_kernel<<<RR, 256>>>(x2, gamma2, beta2, xn, CC);

    // 10. hb = gelu(xn @ W1 + b1)
    {
        dim3 grid(FF / 128, RR / 128, 1);
        sgemm_kernel<false, true><<<grid, 256>>>(RR, FF, CC,
            xn, CC, 0, 0, W1, FF, 0, 0, hb, FF, 0, 0,
            1.f, b1, nullptr, 0, 0, 0, 1);
    }

    // 11. out = x2 + hb @ W2 + b2
    {
        dim3 grid(CC / 128, RR / 128, 1);
        sgemm_kernel<false, false><<<grid, 256>>>(RR, CC, FF,
            hb, FF, 0, 0, W2, CC, 0, 0, out, CC, 0, 0,
            1.f, b2, x2, CC, 0, 0, 1);
    }
}

// round 3
// speedup vs baseline: 7.7146x; 7.7146x over previous
#include <cuda_runtime.h>
#include <math.h>
#include <stdint.h>

#define BB 2
#define NN 2048
#define CC 1024
#define HH 16
#define DD 64
#define FF 4096
#define RR (BB*NN)   // 4096 rows

// ---------------- scratch ----------------
__device__ float g_xn [(size_t)RR*CC];
__device__ float g_q  [(size_t)RR*CC];
__device__ float g_k  [(size_t)RR*CC];
__device__ float g_v  [(size_t)RR*CC];
__device__ float g_vT [(size_t)RR*CC];
__device__ float g_S  [(size_t)BB*HH*NN*NN];   // 536 MB scores
__device__ float g_y  [(size_t)RR*CC];
__device__ float g_x2 [(size_t)RR*CC];
__device__ float g_hb [(size_t)RR*FF];
__device__ float g_Wqt[(size_t)CC*CC];
__device__ float g_Wkt[(size_t)CC*CC];
__device__ float g_Wvt[(size_t)CC*CC];
__device__ float g_Wpt[(size_t)CC*CC];
__device__ float g_W1t[(size_t)FF*CC];
__device__ float g_W2t[(size_t)CC*FF];

// ---------------- helpers ----------------
__device__ __forceinline__ float tf32r(float x) {
    uint32_t u;
    asm("cvt.rna.tf32.f32 %0, %1;" : "=r"(u) : "f"(x));
    return __uint_as_float(u);
}
__device__ __forceinline__ uint32_t smem_u32(const void* p) {
    uint32_t a;
    asm("{ .reg .u64 t; cvta.to.shared.u64 t, %1; cvt.u32.u64 %0, t; }" : "=r"(a) : "l"(p));
    return a;
}
__device__ __forceinline__ void cp16(uint32_t s, const void* g) {
    asm volatile("cp.async.cg.shared.global [%0], [%1], 16;" :: "r"(s), "l"(g));
}
__device__ __forceinline__ void cp_commit() { asm volatile("cp.async.commit_group;" ::: "memory"); }
__device__ __forceinline__ void cp_wait1()  { asm volatile("cp.async.wait_group 1;" ::: "memory"); }
__device__ __forceinline__ void cp_wait0()  { asm volatile("cp.async.wait_group 0;" ::: "memory"); }

__device__ __forceinline__ void mma_tf32(float* d, uint32_t a0, uint32_t a1, uint32_t a2, uint32_t a3,
                                         uint32_t b0, uint32_t b1) {
    asm volatile(
        "mma.sync.aligned.m16n8k8.row.col.f32.tf32.tf32.f32 "
        "{%0,%1,%2,%3}, {%4,%5,%6,%7}, {%8,%9}, {%0,%1,%2,%3};"
        : "+f"(d[0]), "+f"(d[1]), "+f"(d[2]), "+f"(d[3])
        : "r"(a0), "r"(a1), "r"(a2), "r"(a3), "r"(b0), "r"(b1));
}

// ---------------- layernorm (tf32-rounded output) ----------------
__global__ void layernorm_kernel(const float* __restrict__ x,
                                 const float* __restrict__ gamma,
                                 const float* __restrict__ beta,
                                 float* __restrict__ out) {
    __shared__ float red[256];
    int row = blockIdx.x;
    const float* xr = x + (size_t)row * CC;
    float* orow = out + (size_t)row * CC;
    int t = threadIdx.x;

    float s = 0.f;
    for (int i = t; i < CC; i += 256) s += xr[i];
    red[t] = s; __syncthreads();
    for (int st = 128; st > 0; st >>= 1) { if (t < st) red[t] += red[t + st]; __syncthreads(); }
    float mu = red[0] / (float)CC;
    __syncthreads();

    float v = 0.f;
    for (int i = t; i < CC; i += 256) { float d = xr[i] - mu; v += d * d; }
    red[t] = v; __syncthreads();
    for (int st = 128; st > 0; st >>= 1) { if (t < st) red[t] += red[t + st]; __syncthreads(); }
    float inv = rsqrtf(red[0] / (float)CC + 1e-6f);

    for (int i = t; i < CC; i += 256)
        orow[i] = tf32r((xr[i] - mu) * inv * gamma[i] + beta[i]);
}

// ---------------- one-pass softmax (row cached in smem), tf32-rounded out ----------------
__global__ void softmax_kernel(float* __restrict__ S) {
    __shared__ float rowbuf[NN];
    __shared__ float red[256];
    size_t row = blockIdx.x;
    float* p = S + row * (size_t)NN;
    int t = threadIdx.x;

    float mx = -1e30f;
    for (int i = t; i < NN; i += 256) { float v = p[i]; rowbuf[i] = v; mx = fmaxf(mx, v); }
    red[t] = mx; __syncthreads();
    for (int st = 128; st > 0; st >>= 1) { if (t < st) red[t] = fmaxf(red[t], red[t + st]); __syncthreads(); }
    mx = red[0]; __syncthreads();

    float s = 0.f;
    for (int i = t; i < NN; i += 256) { float e = __expf(rowbuf[i] - mx); rowbuf[i] = e; s += e; }
    red[t] = s; __syncthreads();
    for (int st = 128; st > 0; st >>= 1) { if (t < st) red[t] += red[t + st]; __syncthreads(); }
    float invs = 1.f / red[0];

    for (int i = t; i < NN; i += 256) p[i] = tf32r(rowbuf[i] * invs);
}

// ---------------- batched transpose with tf32 rounding ----------------
__global__ void transpose_cvt(const float* __restrict__ in, long ldi, long offIb, long offIh,
                              float* __restrict__ out, long ldo, long offOb, long offOh, int nh) {
    __shared__ float tile[32][33];
    int z = blockIdx.z, zb = z / nh, zh = z % nh;
    in  += (long)zb * offIb + (long)zh * offIh;
    out += (long)zb * offOb + (long)zh * offOh;
    int c0 = blockIdx.x * 32, r0 = blockIdx.y * 32;
    int tx = threadIdx.x, ty = threadIdx.y;   // 32 x 8
    #pragma unroll
    for (int i = 0; i < 32; i += 8)
        tile[ty + i][tx] = in[(long)(r0 + ty + i) * ldi + (c0 + tx)];
    __syncthreads();
    #pragma unroll
    for (int i = 0; i < 32; i += 8)
        out[(long)(c0 + ty + i) * ldo + (r0 + tx)] = tf32r(tile[tx][ty + i]);
}

// ---------------- tf32 mma.sync GEMM ----------------
// C[128 x BN] tile = A[128,K] @ B[N,K]^T (both K-major), tf32 in, fp32 accum.
// 256 threads, BK=16, double-buffered cp.async, smem stride 20 (conflict-free frags).
template<int BN, bool GELU_, bool CVT>
__global__ void __launch_bounds__(256) mma_gemm(
    int K,
    const float* __restrict__ A, long lda, long offAh, long offAb,
    const float* __restrict__ B, long ldb, long offBh, long offBb,
    float* __restrict__ C, long ldc, long offCh, long offCb,
    float alpha, const float* __restrict__ bias,
    const float* __restrict__ resid, long ldr,
    int nh)
{
    constexpr int BM = 128, BK = 16, SS = 20;
    constexpr int WROWS = (BN == 128) ? 2 : 4;
    constexpr int WCOLS = 8 / WROWS;
    constexpr int WM = BM / WROWS;       // 64 or 32
    constexpr int WN = BN / WCOLS;       // 32
    constexpr int MT = WM / 16;          // 4 or 2
    constexpr int NT = WN / 8;           // 4

    __shared__ float As[2][BM * SS];
    __shared__ float Bs[2][BN * SS];

    int z = blockIdx.z, zb = z / nh, zh = z % nh;
    A += (long)zb * offAb + (long)zh * offAh;
    B += (long)zb * offBb + (long)zh * offBh;
    C += (long)zb * offCb + (long)zh * offCh;

    int tid = threadIdx.x;
    int wid = tid >> 5, lane = tid & 31;
    int wrow = wid / WCOLS, wcol = wid % WCOLS;
    int r = lane >> 2, c = lane & 3;

    const float* Ag = A + (long)(blockIdx.y * BM) * lda;
    const float* Bg = B + (long)(blockIdx.x * BN) * ldb;
    const int nk = K / BK;

    uint32_t asb = smem_u32(As), bsb = smem_u32(Bs);

    auto load_chunk = [&](int i, int s) {
        long k0 = (long)i * BK;
        uint32_t ad = asb + s * (BM * SS * 4);
        #pragma unroll
        for (int t = tid; t < BM * 4; t += 256) {
            int m = t >> 2, cc4 = t & 3;
            cp16(ad + m * (SS * 4) + cc4 * 16, Ag + (long)m * lda + k0 + cc4 * 4);
        }
        uint32_t bd = bsb + s * (BN * SS * 4);
        #pragma unroll
        for (int t = tid; t < BN * 4; t += 256) {
            int n = t >> 2, cc4 = t & 3;
            cp16(bd + n * (SS * 4) + cc4 * 16, Bg + (long)n * ldb + k0 + cc4 * 4);
        }
        cp_commit();
    };

    float acc[MT][NT][4];
    #pragma unroll
    for (int i = 0; i < MT; i++)
        #pragma unroll
        for (int j = 0; j < NT; j++)
            #pragma unroll
            for (int e = 0; e < 4; e++) acc[i][j][e] = 0.f;

    load_chunk(0, 0);

    for (int it = 0; it < nk; it++) {
        int s = it & 1;
        if (it + 1 < nk) { load_chunk(it + 1, s ^ 1); cp_wait1(); } else { cp_wait0(); }
        __syncthreads();

        const float* as = As[s];
        const float* bs = Bs[s];
        #pragma unroll
        for (int kk = 0; kk < BK; kk += 8) {
            uint32_t bf[NT][2];
            int nb = wcol * WN;
            #pragma unroll
            for (int j = 0; j < NT; j++) {
                bf[j][0] = __float_as_uint(bs[(nb + j * 8 + r) * SS + kk + c]);
                bf[j][1] = __float_as_uint(bs[(nb + j * 8 + r) * SS + kk + c + 4]);
            }
            #pragma unroll
            for (int i = 0; i < MT; i++) {
                int mb = wrow * WM + i * 16;
                uint32_t a0 = __float_as_uint(as[(mb + r) * SS + kk + c]);
                uint32_t a1 = __float_as_uint(as[(mb + r + 8) * SS + kk + c]);
                uint32_t a2 = __float_as_uint(as[(mb + r) * SS + kk + c + 4]);
                uint32_t a3 = __float_as_uint(as[(mb + r + 8) * SS + kk + c + 4]);
                #pragma unroll
                for (int j = 0; j < NT; j++)
                    mma_tf32(acc[i][j], a0, a1, a2, a3, bf[j][0], bf[j][1]);
            }
        }
        __syncthreads();
    }

    // epilogue: direct float2 stores
    long row0 = (long)blockIdx.y * BM + wrow * WM;
    long col0 = (long)blockIdx.x * BN + wcol * WN;
    #pragma unroll
    for (int i = 0; i < MT; i++) {
        #pragma unroll
        for (int j = 0; j < NT; j++) {
            long gcol = col0 + j * 8 + 2 * c;
            #pragma unroll
            for (int half = 0; half < 2; half++) {
                long grow = row0 + i * 16 + r + half * 8;
                float vx = acc[i][j][half * 2 + 0] * alpha;
                float vy = acc[i][j][half * 2 + 1] * alpha;
                if (bias) { vx += bias[gcol]; vy += bias[gcol + 1]; }
                if (GELU_) {
                    vx = 0.5f * vx * (1.f + erff(vx * 0.70710678118654752f));
                    vy = 0.5f * vy * (1.f + erff(vy * 0.70710678118654752f));
                }
                if (resid) {
                    const float2 rr = *reinterpret_cast<const float2*>(resid + grow * ldr + gcol);
                    vx += rr.x; vy += rr.y;
                }
                if (CVT) { vx = tf32r(vx); vy = tf32r(vy); }
                float2 o; o.x = vx; o.y = vy;
                *reinterpret_cast<float2*>(C + grow * ldc + gcol) = o;
            }
        }
    }
}

// ---------------- host ----------------
static float* sym_addr(const void* s) {
    void* p = nullptr;
    cudaGetSymbolAddress(&p, s);
    return (float*)p;
}

extern "C" void kernel_launch(void* const* d_in, const int* in_sizes, int n_in,
                              void* d_out, int out_size) {
    const float* x      = (const float*)d_in[0];
    const float* Wq     = (const float*)d_in[1];
    const float* Wk     = (const float*)d_in[2];
    const float* Wv     = (const float*)d_in[3];
    const float* Wp     = (const float*)d_in[4];
    const float* bp     = (const float*)d_in[5];
    const float* W1     = (const float*)d_in[6];
    const float* b1     = (const float*)d_in[7];
    const float* W2     = (const float*)d_in[8];
    const float* b2     = (const float*)d_in[9];
    const float* gamma1 = (const float*)d_in[10];
    const float* beta1  = (const float*)d_in[11];
    const float* gamma2 = (const float*)d_in[12];
    const float* beta2  = (const float*)d_in[13];
    float* out = (float*)d_out;

    float* xn  = sym_addr(g_xn);
    float* q   = sym_addr(g_q);
    float* k   = sym_addr(g_k);
    float* v   = sym_addr(g_v);
    float* vT  = sym_addr(g_vT);
    float* S   = sym_addr(g_S);
    float* y   = sym_addr(g_y);
    float* x2  = sym_addr(g_x2);
    float* hb  = sym_addr(g_hb);
    float* Wqt = sym_addr(g_Wqt);
    float* Wkt = sym_addr(g_Wkt);
    float* Wvt = sym_addr(g_Wvt);
    float* Wpt = sym_addr(g_Wpt);
    float* W1t = sym_addr(g_W1t);
    float* W2t = sym_addr(g_W2t);

    dim3 tb(32, 8);

    // weight transposes (tf32-rounded): Wt[n][k] = W[k][n]
    transpose_cvt<<<dim3(CC/32, CC/32, 1), tb>>>(Wq, CC, 0, 0, Wqt, CC, 0, 0, 1);
    transpose_cvt<<<dim3(CC/32, CC/32, 1), tb>>>(Wk, CC, 0, 0, Wkt, CC, 0, 0, 1);
    transpose_cvt<<<dim3(CC/32, CC/32, 1), tb>>>(Wv, CC, 0, 0, Wvt, CC, 0, 0, 1);
    transpose_cvt<<<dim3(CC/32, CC/32, 1), tb>>>(Wp, CC, 0, 0, Wpt, CC, 0, 0, 1);
    transpose_cvt<<<dim3(FF/32, CC/32, 1), tb>>>(W1, FF, 0, 0, W1t, CC, 0, 0, 1);
    transpose_cvt<<<dim3(CC/32, FF/32, 1), tb>>>(W2, CC, 0, 0, W2t, FF, 0, 0, 1);

    // LN1
    layernorm_kernel<<<RR, 256>>>(x, gamma1, beta1, xn);

    // QKV: [4096,1024] = xn @ Wt^T ; q,k,y,hb tf32-rounded (operands of later GEMMs)
    {
        dim3 g(CC/128, RR/128, 1);
        mma_gemm<128, false, true ><<<g, 256>>>(CC,
            xn, CC, 0, 0, Wqt, CC, 0, 0, q, CC, 0, 0, 1.f, nullptr, nullptr, 0, 1);
        mma_gemm<128, false, true ><<<g, 256>>>(CC,
            xn, CC, 0, 0, Wkt, CC, 0, 0, k, CC, 0, 0, 1.f, nullptr, nullptr, 0, 1);
        mma_gemm<128, false, false><<<g, 256>>>(CC,
            xn, CC, 0, 0, Wvt, CC, 0, 0, v, CC, 0, 0, 1.f, nullptr, nullptr, 0, 1);
    }

    // vT[b,h][d][token] = tf32(v[b][token][h*64+d])
    transpose_cvt<<<dim3(DD/32, NN/32, BB*HH), tb>>>(
        v, CC, (long)NN*CC, DD, vT, NN, (long)HH*DD*NN, (long)DD*NN, HH);

    // scores: S_bh = 0.125 * q_bh @ k_bh^T   (K = 64)
    mma_gemm<128, false, false><<<dim3(NN/128, NN/128, BB*HH), 256>>>(DD,
        q, CC, DD, (long)NN*CC,
        k, CC, DD, (long)NN*CC,
        S, NN, (long)NN*NN, (long)HH*NN*NN,
        0.125f, nullptr, nullptr, 0, HH);

    // softmax rows (tf32-rounded probabilities)
    softmax_kernel<<<BB*HH*NN, 256>>>(S);

    // y_bh = P_bh @ vT_bh^T  (K = 2048, N = 64)
    mma_gemm<64, false, true><<<dim3(1, NN/128, BB*HH), 256>>>(NN,
        S,  NN, (long)NN*NN, (long)HH*NN*NN,
        vT, NN, (long)DD*NN, (long)HH*DD*NN,
        y,  CC, DD, (long)NN*CC,
        1.f, nullptr, nullptr, 0, HH);

    // x2 = x + y @ Wp + bp
    mma_gemm<128, false, false><<<dim3(CC/128, RR/128, 1), 256>>>(CC,
        y, CC, 0, 0, Wpt, CC, 0, 0, x2, CC, 0, 0, 1.f, bp, x, CC, 1);

    // LN2
    layernorm_kernel<<<RR, 256>>>(x2, gamma2, beta2, xn);

    // hb = tf32(gelu(xn @ W1 + b1))
    mma_gemm<128, true, true><<<dim3(FF/128, RR/128, 1), 256>>>(CC,
        xn, CC, 0, 0, W1t, CC, 0, 0, hb, FF, 0, 0, 1.f, b1, nullptr, 0, 1);

    // out = x2 + hb @ W2 + b2
    mma_gemm<128, false, false><<<dim3(CC/128, RR/128, 1), 256>>>(FF,
        hb, FF, 0, 0, W2t, FF, 0, 0, out, CC, 0, 0, 1.f, b2, x2, CC, 1);
}

// round 4
// speedup vs baseline: 10.3453x; 1.3410x over previous
#include <cuda_runtime.h>
#include <math.h>
#include <stdint.h>

#define BB 2
#define NN 2048
#define CC 1024
#define HH 16
#define DD 64
#define FF 4096
#define RR (BB*NN)   // 4096 rows

// ---------------- scratch ----------------
__device__ float g_xn   [(size_t)RR*CC];
__device__ float g_qkv  [(size_t)RR*3*CC];
__device__ float g_y    [(size_t)RR*CC];
__device__ float g_x2   [(size_t)RR*CC];
__device__ float g_hb   [(size_t)RR*FF];
__device__ float g_Wqkvt[(size_t)3*CC*CC];
__device__ float g_Wpt  [(size_t)CC*CC];
__device__ float g_W1t  [(size_t)FF*CC];
__device__ float g_W2t  [(size_t)CC*FF];

// ---------------- helpers ----------------
__device__ __forceinline__ float tf32r(float x) {
    uint32_t u;
    asm("cvt.rna.tf32.f32 %0, %1;" : "=r"(u) : "f"(x));
    return __uint_as_float(u);
}
__device__ __forceinline__ uint32_t smem_u32(const void* p) {
    uint32_t a;
    asm("{ .reg .u64 t; cvta.to.shared.u64 t, %1; cvt.u32.u64 %0, t; }" : "=r"(a) : "l"(p));
    return a;
}
__device__ __forceinline__ void cp16(uint32_t s, const void* g) {
    asm volatile("cp.async.cg.shared.global [%0], [%1], 16;" :: "r"(s), "l"(g));
}
__device__ __forceinline__ void cp_commit() { asm volatile("cp.async.commit_group;" ::: "memory"); }
__device__ __forceinline__ void cp_wait1()  { asm volatile("cp.async.wait_group 1;" ::: "memory"); }
__device__ __forceinline__ void cp_wait0()  { asm volatile("cp.async.wait_group 0;" ::: "memory"); }

__device__ __forceinline__ void mma_tf32(float* d, uint32_t a0, uint32_t a1, uint32_t a2, uint32_t a3,
                                         uint32_t b0, uint32_t b1) {
    asm volatile(
        "mma.sync.aligned.m16n8k8.row.col.f32.tf32.tf32.f32 "
        "{%0,%1,%2,%3}, {%4,%5,%6,%7}, {%8,%9}, {%0,%1,%2,%3};"
        : "+f"(d[0]), "+f"(d[1]), "+f"(d[2]), "+f"(d[3])
        : "r"(a0), "r"(a1), "r"(a2), "r"(a3), "r"(b0), "r"(b1));
}

// ---------------- layernorm (tf32-rounded output) ----------------
__global__ void layernorm_kernel(const float* __restrict__ x,
                                 const float* __restrict__ gamma,
                                 const float* __restrict__ beta,
                                 float* __restrict__ out) {
    __shared__ float red[256];
    int row = blockIdx.x;
    const float* xr = x + (size_t)row * CC;
    float* orow = out + (size_t)row * CC;
    int t = threadIdx.x;

    float s = 0.f;
    for (int i = t; i < CC; i += 256) s += xr[i];
    red[t] = s; __syncthreads();
    for (int st = 128; st > 0; st >>= 1) { if (t < st) red[t] += red[t + st]; __syncthreads(); }
    float mu = red[0] / (float)CC;
    __syncthreads();

    float v = 0.f;
    for (int i = t; i < CC; i += 256) { float d = xr[i] - mu; v += d * d; }
    red[t] = v; __syncthreads();
    for (int st = 128; st > 0; st >>= 1) { if (t < st) red[t] += red[t + st]; __syncthreads(); }
    float inv = rsqrtf(red[0] / (float)CC + 1e-6f);

    for (int i = t; i < CC; i += 256)
        orow[i] = tf32r((xr[i] - mu) * inv * gamma[i] + beta[i]);
}

// ---------------- transpose with tf32 rounding + scale ----------------
__global__ void transpose_cvt(const float* __restrict__ in, long ldi,
                              float* __restrict__ out, long ldo, float alpha) {
    __shared__ float tile[32][33];
    int c0 = blockIdx.x * 32, r0 = blockIdx.y * 32;
    int tx = threadIdx.x, ty = threadIdx.y;   // 32 x 8
    #pragma unroll
    for (int i = 0; i < 32; i += 8)
        tile[ty + i][tx] = in[(long)(r0 + ty + i) * ldi + (c0 + tx)];
    __syncthreads();
    #pragma unroll
    for (int i = 0; i < 32; i += 8)
        out[(long)(c0 + ty + i) * ldo + (r0 + tx)] = tf32r(tile[tx][ty + i] * alpha);
}

// ---------------- tf32 mma.sync GEMM (unchanged core from R3) ----------------
template<int BN, bool GELU_, bool CVT>
__global__ void __launch_bounds__(256) mma_gemm(
    int K,
    const float* __restrict__ A, long lda,
    const float* __restrict__ B, long ldb,
    float* __restrict__ C, long ldc,
    float alpha, const float* __restrict__ bias,
    const float* __restrict__ resid, long ldr)
{
    constexpr int BM = 128, BK = 16, SS = 20;
    constexpr int WROWS = (BN == 128) ? 2 : 4;
    constexpr int WCOLS = 8 / WROWS;
    constexpr int WM = BM / WROWS;
    constexpr int WN = BN / WCOLS;
    constexpr int MT = WM / 16;
    constexpr int NT = WN / 8;

    __shared__ float As[2][BM * SS];
    __shared__ float Bs[2][BN * SS];

    int tid = threadIdx.x;
    int wid = tid >> 5, lane = tid & 31;
    int wrow = wid / WCOLS, wcol = wid % WCOLS;
    int r = lane >> 2, c = lane & 3;

    const float* Ag = A + (long)(blockIdx.y * BM) * lda;
    const float* Bg = B + (long)(blockIdx.x * BN) * ldb;
    const int nk = K / BK;

    uint32_t asb = smem_u32(As), bsb = smem_u32(Bs);

    auto load_chunk = [&](int i, int s) {
        long k0 = (long)i * BK;
        uint32_t ad = asb + s * (BM * SS * 4);
        #pragma unroll
        for (int t = tid; t < BM * 4; t += 256) {
            int m = t >> 2, cc4 = t & 3;
            cp16(ad + m * (SS * 4) + cc4 * 16, Ag + (long)m * lda + k0 + cc4 * 4);
        }
        uint32_t bd = bsb + s * (BN * SS * 4);
        #pragma unroll
        for (int t = tid; t < BN * 4; t += 256) {
            int n = t >> 2, cc4 = t & 3;
            cp16(bd + n * (SS * 4) + cc4 * 16, Bg + (long)n * ldb + k0 + cc4 * 4);
        }
        cp_commit();
    };

    float acc[MT][NT][4];
    #pragma unroll
    for (int i = 0; i < MT; i++)
        #pragma unroll
        for (int j = 0; j < NT; j++)
            #pragma unroll
            for (int e = 0; e < 4; e++) acc[i][j][e] = 0.f;

    load_chunk(0, 0);

    for (int it = 0; it < nk; it++) {
        int s = it & 1;
        if (it + 1 < nk) { load_chunk(it + 1, s ^ 1); cp_wait1(); } else { cp_wait0(); }
        __syncthreads();

        const float* as = As[s];
        const float* bs = Bs[s];
        #pragma unroll
        for (int kk = 0; kk < BK; kk += 8) {
            uint32_t bf[NT][2];
            int nb = wcol * WN;
            #pragma unroll
            for (int j = 0; j < NT; j++) {
                bf[j][0] = __float_as_uint(bs[(nb + j * 8 + r) * SS + kk + c]);
                bf[j][1] = __float_as_uint(bs[(nb + j * 8 + r) * SS + kk + c + 4]);
            }
            #pragma unroll
            for (int i = 0; i < MT; i++) {
                int mb = wrow * WM + i * 16;
                uint32_t a0 = __float_as_uint(as[(mb + r) * SS + kk + c]);
                uint32_t a1 = __float_as_uint(as[(mb + r + 8) * SS + kk + c]);
                uint32_t a2 = __float_as_uint(as[(mb + r) * SS + kk + c + 4]);
                uint32_t a3 = __float_as_uint(as[(mb + r + 8) * SS + kk + c + 4]);
                #pragma unroll
                for (int j = 0; j < NT; j++)
                    mma_tf32(acc[i][j], a0, a1, a2, a3, bf[j][0], bf[j][1]);
            }
        }
        __syncthreads();
    }

    long row0 = (long)blockIdx.y * BM + wrow * WM;
    long col0 = (long)blockIdx.x * BN + wcol * WN;
    #pragma unroll
    for (int i = 0; i < MT; i++) {
        #pragma unroll
        for (int j = 0; j < NT; j++) {
            long gcol = col0 + j * 8 + 2 * c;
            #pragma unroll
            for (int half = 0; half < 2; half++) {
                long grow = row0 + i * 16 + r + half * 8;
                float vx = acc[i][j][half * 2 + 0] * alpha;
                float vy = acc[i][j][half * 2 + 1] * alpha;
                if (bias) { vx += bias[gcol]; vy += bias[gcol + 1]; }
                if (GELU_) {
                    vx = 0.5f * vx * (1.f + erff(vx * 0.70710678118654752f));
                    vy = 0.5f * vy * (1.f + erff(vy * 0.70710678118654752f));
                }
                if (resid) {
                    const float2 rr = *reinterpret_cast<const float2*>(resid + grow * ldr + gcol);
                    vx += rr.x; vy += rr.y;
                }
                if (CVT) { vx = tf32r(vx); vy = tf32r(vy); }
                float2 o; o.x = vx; o.y = vy;
                *reinterpret_cast<float2*>(C + grow * ldc + gcol) = o;
            }
        }
    }
}

// ---------------- flash attention ----------------
// Per CTA: 128 q rows of one (b,h); loop over 32 kv tiles of 64.
// qkv packed [RR][3072]: q at col h*64, k at 1024+h*64, v at 2048+h*64 (all tf32-rounded).
// Writes y[token][h*64+d], tf32-rounded.
#define QS 68
#define KS 68
#define VS 72
#define PS 68
#define FLASH_SMEM ((128*QS + 2*64*KS + 2*64*VS + 128*PS) * 4)

__global__ void __launch_bounds__(256) flash_kernel(const float* __restrict__ qkv,
                                                    float* __restrict__ y) {
    extern __shared__ float fs[];
    float* Qs = fs;                       // 128 x QS
    float* Ks = Qs + 128 * QS;            // 2 x 64 x KS
    float* Vs = Ks + 2 * 64 * KS;         // 2 x 64 x VS
    float* Ps = Vs + 2 * 64 * VS;         // 128 x PS

    int tid = threadIdx.x;
    int wid = tid >> 5, lane = tid & 31;
    int r = lane >> 2, c = lane & 3;
    int mb = wid * 16;

    int bh = blockIdx.y;
    int b = bh >> 4, h = bh & 15;
    long qrow0 = (long)b * NN + (long)blockIdx.x * 128;
    long kvrow0 = (long)b * NN;
    const float* qg = qkv + qrow0 * 3072 + h * 64;
    const float* kg = qkv + kvrow0 * 3072 + 1024 + h * 64;
    const float* vg = qkv + kvrow0 * 3072 + 2048 + h * 64;

    uint32_t qsb = smem_u32(Qs), ksb = smem_u32(Ks), vsb = smem_u32(Vs);

    // Q load (group 0)
    #pragma unroll
    for (int t = tid; t < 128 * 16; t += 256) {
        int row = t >> 4, ch = t & 15;
        cp16(qsb + (row * QS + ch * 4) * 4, qg + (long)row * 3072 + ch * 4);
    }
    cp_commit();

    auto load_kv = [&](int i, int s) {
        long rb = (long)i * 64;
        #pragma unroll
        for (int t = tid; t < 64 * 16; t += 256) {
            int row = t >> 4, ch = t & 15;
            cp16(ksb + ((s * 64 + row) * KS + ch * 4) * 4, kg + (rb + row) * 3072 + ch * 4);
        }
        #pragma unroll
        for (int t = tid; t < 64 * 16; t += 256) {
            int row = t >> 4, ch = t & 15;
            cp16(vsb + ((s * 64 + row) * VS + ch * 4) * 4, vg + (rb + row) * 3072 + ch * 4);
        }
        cp_commit();
    };

    load_kv(0, 0);

    float m0 = -1e30f, m1 = -1e30f, l0 = 0.f, l1 = 0.f;
    float o[8][4];
    #pragma unroll
    for (int j = 0; j < 8; j++)
        #pragma unroll
        for (int e = 0; e < 4; e++) o[j][e] = 0.f;

    const int niter = NN / 64;   // 32
    for (int it = 0; it < niter; it++) {
        int s = it & 1;
        if (it + 1 < niter) { load_kv(it + 1, s ^ 1); cp_wait1(); } else { cp_wait0(); }
        __syncthreads();

        // ---- S = Q @ K^T (128x64 tile; warp: 16 rows x 64 cols) ----
        float sacc[8][4];
        #pragma unroll
        for (int j = 0; j < 8; j++)
            #pragma unroll
            for (int e = 0; e < 4; e++) sacc[j][e] = 0.f;

        const float* ks = Ks + s * 64 * KS;
        #pragma unroll
        for (int kk = 0; kk < 64; kk += 8) {
            uint32_t a0 = __float_as_uint(Qs[(mb + r) * QS + kk + c]);
            uint32_t a1 = __float_as_uint(Qs[(mb + r + 8) * QS + kk + c]);
            uint32_t a2 = __float_as_uint(Qs[(mb + r) * QS + kk + c + 4]);
            uint32_t a3 = __float_as_uint(Qs[(mb + r + 8) * QS + kk + c + 4]);
            #pragma unroll
            for (int j = 0; j < 8; j++) {
                uint32_t b0 = __float_as_uint(ks[(j * 8 + r) * KS + kk + c]);
                uint32_t b1 = __float_as_uint(ks[(j * 8 + r) * KS + kk + c + 4]);
                mma_tf32(sacc[j], a0, a1, a2, a3, b0, b1);
            }
        }

        // ---- online softmax (rows r and r+8 of this warp's 16-row band) ----
        float mx0 = -1e30f, mx1 = -1e30f;
        #pragma unroll
        for (int j = 0; j < 8; j++) {
            mx0 = fmaxf(mx0, fmaxf(sacc[j][0], sacc[j][1]));
            mx1 = fmaxf(mx1, fmaxf(sacc[j][2], sacc[j][3]));
        }
        #pragma unroll
        for (int off = 1; off <= 2; off <<= 1) {
            mx0 = fmaxf(mx0, __shfl_xor_sync(0xffffffffu, mx0, off));
            mx1 = fmaxf(mx1, __shfl_xor_sync(0xffffffffu, mx1, off));
        }
        float mn0 = fmaxf(m0, mx0), mn1 = fmaxf(m1, mx1);
        float sc0 = __expf(m0 - mn0), sc1 = __expf(m1 - mn1);
        float sum0 = 0.f, sum1 = 0.f;
        #pragma unroll
        for (int j = 0; j < 8; j++) {
            float e0 = __expf(sacc[j][0] - mn0);
            float e1 = __expf(sacc[j][1] - mn0);
            float e2 = __expf(sacc[j][2] - mn1);
            float e3 = __expf(sacc[j][3] - mn1);
            sum0 += e0 + e1; sum1 += e2 + e3;
            float2 p0; p0.x = tf32r(e0); p0.y = tf32r(e1);
            float2 p1; p1.x = tf32r(e2); p1.y = tf32r(e3);
            *reinterpret_cast<float2*>(&Ps[(mb + r) * PS + j * 8 + 2 * c]) = p0;
            *reinterpret_cast<float2*>(&Ps[(mb + r + 8) * PS + j * 8 + 2 * c]) = p1;
        }
        #pragma unroll
        for (int off = 1; off <= 2; off <<= 1) {
            sum0 += __shfl_xor_sync(0xffffffffu, sum0, off);
            sum1 += __shfl_xor_sync(0xffffffffu, sum1, off);
        }
        l0 = l0 * sc0 + sum0;
        l1 = l1 * sc1 + sum1;
        m0 = mn0; m1 = mn1;
        #pragma unroll
        for (int j = 0; j < 8; j++) {
            o[j][0] *= sc0; o[j][1] *= sc0; o[j][2] *= sc1; o[j][3] *= sc1;
        }
        __syncwarp();

        // ---- O += P @ V  (A = Ps rows [mb,mb+16), k = 64 kv; B[n=d][k=kv] = Vs[kv][d]) ----
        const float* vs = Vs + s * 64 * VS;
        #pragma unroll
        for (int kk = 0; kk < 64; kk += 8) {
            uint32_t a0 = __float_as_uint(Ps[(mb + r) * PS + kk + c]);
            uint32_t a1 = __float_as_uint(Ps[(mb + r + 8) * PS + kk + c]);
            uint32_t a2 = __float_as_uint(Ps[(mb + r) * PS + kk + c + 4]);
            uint32_t a3 = __float_as_uint(Ps[(mb + r + 8) * PS + kk + c + 4]);
            #pragma unroll
            for (int j = 0; j < 8; j++) {
                uint32_t b0 = __float_as_uint(vs[(kk + c) * VS + j * 8 + r]);
                uint32_t b1 = __float_as_uint(vs[(kk + c + 4) * VS + j * 8 + r]);
                mma_tf32(o[j], a0, a1, a2, a3, b0, b1);
            }
        }
        __syncwarp();
        __syncthreads();
    }

    // ---- finalize: O /= l, write y ----
    float inv0 = 1.f / l0, inv1 = 1.f / l1;
    long grow0 = qrow0 + mb + r;
    long grow1 = grow0 + 8;
    #pragma unroll
    for (int j = 0; j < 8; j++) {
        long gcol = h * 64 + j * 8 + 2 * c;
        float2 o0; o0.x = tf32r(o[j][0] * inv0); o0.y = tf32r(o[j][1] * inv0);
        float2 o1; o1.x = tf32r(o[j][2] * inv1); o1.y = tf32r(o[j][3] * inv1);
        *reinterpret_cast<float2*>(y + grow0 * CC + gcol) = o0;
        *reinterpret_cast<float2*>(y + grow1 * CC + gcol) = o1;
    }
}

// ---------------- host ----------------
static float* sym_addr(const void* s) {
    void* p = nullptr;
    cudaGetSymbolAddress(&p, s);
    return (float*)p;
}

extern "C" void kernel_launch(void* const* d_in, const int* in_sizes, int n_in,
                              void* d_out, int out_size) {
    const float* x      = (const float*)d_in[0];
    const float* Wq     = (const float*)d_in[1];
    const float* Wk     = (const float*)d_in[2];
    const float* Wv     = (const float*)d_in[3];
    const float* Wp     = (const float*)d_in[4];
    const float* bp     = (const float*)d_in[5];
    const float* W1     = (const float*)d_in[6];
    const float* b1     = (const float*)d_in[7];
    const float* W2     = (const float*)d_in[8];
    const float* b2     = (const float*)d_in[9];
    const float* gamma1 = (const float*)d_in[10];
    const float* beta1  = (const float*)d_in[11];
    const float* gamma2 = (const float*)d_in[12];
    const float* beta2  = (const float*)d_in[13];
    float* out = (float*)d_out;

    float* xn    = sym_addr(g_xn);
    float* qkv   = sym_addr(g_qkv);
    float* y     = sym_addr(g_y);
    float* x2    = sym_addr(g_x2);
    float* hb    = sym_addr(g_hb);
    float* Wqkvt = sym_addr(g_Wqkvt);
    float* Wpt   = sym_addr(g_Wpt);
    float* W1t   = sym_addr(g_W1t);
    float* W2t   = sym_addr(g_W2t);

    cudaFuncSetAttribute(flash_kernel, cudaFuncAttributeMaxDynamicSharedMemorySize, FLASH_SMEM);

    dim3 tb(32, 8);

    // weight transposes (tf32-rounded); q scale folded into Wq (0.125 exact)
    transpose_cvt<<<dim3(CC/32, CC/32), tb>>>(Wq, CC, Wqkvt,               CC, 0.125f);
    transpose_cvt<<<dim3(CC/32, CC/32), tb>>>(Wk, CC, Wqkvt + (size_t)CC*CC,   CC, 1.f);
    transpose_cvt<<<dim3(CC/32, CC/32), tb>>>(Wv, CC, Wqkvt + (size_t)2*CC*CC, CC, 1.f);
    transpose_cvt<<<dim3(CC/32, CC/32), tb>>>(Wp, CC, Wpt, CC, 1.f);
    transpose_cvt<<<dim3(FF/32, CC/32), tb>>>(W1, FF, W1t, CC, 1.f);
    transpose_cvt<<<dim3(CC/32, FF/32), tb>>>(W2, CC, W2t, FF, 1.f);

    // LN1
    layernorm_kernel<<<RR, 256>>>(x, gamma1, beta1, xn);

    // fused QKV: [4096, 3072] = xn @ Wqkvt^T (tf32-rounded outputs)
    mma_gemm<128, false, true><<<dim3(3*CC/128, RR/128), 256>>>(CC,
        xn, CC, Wqkvt, CC, qkv, 3*CC, 1.f, nullptr, nullptr, 0);

    // flash attention -> y (tf32-rounded)
    flash_kernel<<<dim3(NN/128, BB*HH), 256, FLASH_SMEM>>>(qkv, y);

    // x2 = x + y @ Wp + bp
    mma_gemm<128, false, false><<<dim3(CC/128, RR/128), 256>>>(CC,
        y, CC, Wpt, CC, x2, CC, 1.f, bp, x, CC);

    // LN2
    layernorm_kernel<<<RR, 256>>>(x2, gamma2, beta2, xn);

    // hb = tf32(gelu(xn @ W1 + b1))
    mma_gemm<128, true, true><<<dim3(FF/128, RR/128), 256>>>(CC,
        xn, CC, W1t, CC, hb, FF, 1.f, b1, nullptr, 0);

    // out = x2 + hb @ W2 + b2
    mma_gemm<128, false, false><<<dim3(CC/128, RR/128), 256>>>(FF,
        hb, FF, W2t, FF, out, CC, 1.f, b2, x2, CC);
}

// round 5
// speedup vs baseline: 19.1735x; 1.8534x over previous
#include <cuda_runtime.h>
#include <cuda_fp16.h>
#include <math.h>
#include <stdint.h>

#define BB 2
#define NN 2048
#define CC 1024
#define HH 16
#define DD 64
#define FF 4096
#define RR (BB*NN)   // 4096 rows

// ---------------- scratch ----------------
__device__ __align__(16) __half g_xn   [(size_t)RR*CC];
__device__ __align__(16) __half g_qkv  [(size_t)RR*3*CC];
__device__ __align__(16) __half g_y    [(size_t)RR*CC];
__device__ __align__(16) float  g_x2   [(size_t)RR*CC];
__device__ __align__(16) __half g_hb   [(size_t)RR*FF];
__device__ __align__(16) __half g_Wqkvt[(size_t)3*CC*CC];
__device__ __align__(16) __half g_Wpt  [(size_t)CC*CC];
__device__ __align__(16) __half g_W1t  [(size_t)FF*CC];
__device__ __align__(16) __half g_W2t  [(size_t)CC*FF];

// ---------------- helpers ----------------
__device__ __forceinline__ uint32_t smem_u32(const void* p) {
    uint32_t a;
    asm("{ .reg .u64 t; cvta.to.shared.u64 t, %1; cvt.u32.u64 %0, t; }" : "=r"(a) : "l"(p));
    return a;
}
__device__ __forceinline__ void cp16(uint32_t s, const void* g) {
    asm volatile("cp.async.cg.shared.global [%0], [%1], 16;" :: "r"(s), "l"(g));
}
__device__ __forceinline__ void cp_commit() { asm volatile("cp.async.commit_group;" ::: "memory"); }
__device__ __forceinline__ void cp_wait1()  { asm volatile("cp.async.wait_group 1;" ::: "memory"); }
__device__ __forceinline__ void cp_wait0()  { asm volatile("cp.async.wait_group 0;" ::: "memory"); }

__device__ __forceinline__ void ldmx4(uint32_t& r0, uint32_t& r1, uint32_t& r2, uint32_t& r3, uint32_t a) {
    asm volatile("ldmatrix.sync.aligned.m8n8.x4.shared.b16 {%0,%1,%2,%3}, [%4];"
                 : "=r"(r0), "=r"(r1), "=r"(r2), "=r"(r3) : "r"(a));
}
__device__ __forceinline__ void ldmx2(uint32_t& r0, uint32_t& r1, uint32_t a) {
    asm volatile("ldmatrix.sync.aligned.m8n8.x2.shared.b16 {%0,%1}, [%2];"
                 : "=r"(r0), "=r"(r1) : "r"(a));
}
__device__ __forceinline__ void ldmx2t(uint32_t& r0, uint32_t& r1, uint32_t a) {
    asm volatile("ldmatrix.sync.aligned.m8n8.x2.trans.shared.b16 {%0,%1}, [%2];"
                 : "=r"(r0), "=r"(r1) : "r"(a));
}
__device__ __forceinline__ void mma_h(float* d, uint32_t a0, uint32_t a1, uint32_t a2, uint32_t a3,
                                      uint32_t b0, uint32_t b1) {
    asm volatile(
        "mma.sync.aligned.m16n8k16.row.col.f32.f16.f16.f32 "
        "{%0,%1,%2,%3}, {%4,%5,%6,%7}, {%8,%9}, {%0,%1,%2,%3};"
        : "+f"(d[0]), "+f"(d[1]), "+f"(d[2]), "+f"(d[3])
        : "r"(a0), "r"(a1), "r"(a2), "r"(a3), "r"(b0), "r"(b1));
}

// ---------------- layernorm (fp32 in, fp16 out) ----------------
__global__ void layernorm_kernel(const float* __restrict__ x,
                                 const float* __restrict__ gamma,
                                 const float* __restrict__ beta,
                                 __half* __restrict__ out) {
    __shared__ float red[256];
    int row = blockIdx.x;
    const float* xr = x + (size_t)row * CC;
    __half* orow = out + (size_t)row * CC;
    int t = threadIdx.x;

    float s = 0.f;
    for (int i = t; i < CC; i += 256) s += xr[i];
    red[t] = s; __syncthreads();
    for (int st = 128; st > 0; st >>= 1) { if (t < st) red[t] += red[t + st]; __syncthreads(); }
    float mu = red[0] / (float)CC;
    __syncthreads();

    float v = 0.f;
    for (int i = t; i < CC; i += 256) { float d = xr[i] - mu; v += d * d; }
    red[t] = v; __syncthreads();
    for (int st = 128; st > 0; st >>= 1) { if (t < st) red[t] += red[t + st]; __syncthreads(); }
    float inv = rsqrtf(red[0] / (float)CC + 1e-6f);

    for (int i = t; i < CC; i += 256)
        orow[i] = __float2half_rn((xr[i] - mu) * inv * gamma[i] + beta[i]);
}

// ---------------- transpose fp32 -> fp16 with scale ----------------
__global__ void transpose_cvt(const float* __restrict__ in, long ldi,
                              __half* __restrict__ out, long ldo, float alpha) {
    __shared__ float tile[32][33];
    int c0 = blockIdx.x * 32, r0 = blockIdx.y * 32;
    int tx = threadIdx.x, ty = threadIdx.y;   // 32 x 8
    #pragma unroll
    for (int i = 0; i < 32; i += 8)
        tile[ty + i][tx] = in[(long)(r0 + ty + i) * ldi + (c0 + tx)];
    __syncthreads();
    #pragma unroll
    for (int i = 0; i < 32; i += 8)
        out[(long)(c0 + ty + i) * ldo + (r0 + tx)] = __float2half_rn(tile[tx][ty + i] * alpha);
}

// ---------------- fp16 mma GEMM ----------------
// C[128x128] tile = A[M,K] @ B[N,K]^T, fp16 operands, fp32 accum.
// 256 threads, BK=32, double-buffered cp.async, ldmatrix fragments.
template<bool GELU_, bool HOUT>
__global__ void __launch_bounds__(256) hgemm(
    int K,
    const __half* __restrict__ A, long lda,
    const __half* __restrict__ B, long ldb,
    void* __restrict__ Cv, long ldc,
    const float* __restrict__ bias,
    const float* __restrict__ resid, long ldr)
{
    constexpr int SS = 40;   // halfs per smem row (32 + 8 pad)
    __shared__ __half As[2][128 * SS];
    __shared__ __half Bs[2][128 * SS];

    int tid = threadIdx.x;
    int wid = tid >> 5, lane = tid & 31;
    int wrow = wid >> 2, wcol = wid & 3;          // 2 x 4 warps
    int r = lane >> 2, c = lane & 3;
    int mb = wrow * 64, nb = wcol * 32;

    const __half* Ag = A + (long)(blockIdx.y * 128) * lda;
    const __half* Bg = B + (long)(blockIdx.x * 128) * ldb;
    const int nk = K / 32;

    uint32_t asb = smem_u32(As), bsb = smem_u32(Bs);
    const uint32_t STAGE = 128 * SS * 2;

    auto load_chunk = [&](int i, int s) {
        long k0 = (long)i * 32;
        uint32_t ad = asb + s * STAGE;
        #pragma unroll
        for (int t = tid; t < 512; t += 256) {
            int m = t >> 2, ch = t & 3;
            cp16(ad + (m * SS + ch * 8) * 2, Ag + (long)m * lda + k0 + ch * 8);
        }
        uint32_t bd = bsb + s * STAGE;
        #pragma unroll
        for (int t = tid; t < 512; t += 256) {
            int n = t >> 2, ch = t & 3;
            cp16(bd + (n * SS + ch * 8) * 2, Bg + (long)n * ldb + k0 + ch * 8);
        }
        cp_commit();
    };

    float acc[4][4][4];
    #pragma unroll
    for (int i = 0; i < 4; i++)
        #pragma unroll
        for (int j = 0; j < 4; j++)
            #pragma unroll
            for (int e = 0; e < 4; e++) acc[i][j][e] = 0.f;

    load_chunk(0, 0);

    int l7 = lane & 7, l8 = lane & 8, lh = (lane >> 4) << 3;

    for (int it = 0; it < nk; it++) {
        int s = it & 1;
        if (it + 1 < nk) { load_chunk(it + 1, s ^ 1); cp_wait1(); } else { cp_wait0(); }
        __syncthreads();

        uint32_t as = asb + s * STAGE;
        uint32_t bs = bsb + s * STAGE;
        #pragma unroll
        for (int kk = 0; kk < 32; kk += 16) {
            uint32_t bf[4][2];
            #pragma unroll
            for (int j = 0; j < 4; j++)
                ldmx2(bf[j][0], bf[j][1], bs + ((nb + j * 8 + l7) * SS + kk + l8) * 2);
            #pragma unroll
            for (int i = 0; i < 4; i++) {
                uint32_t a0, a1, a2, a3;
                ldmx4(a0, a1, a2, a3, as + ((mb + i * 16 + l7 + l8) * SS + kk + lh) * 2);
                #pragma unroll
                for (int j = 0; j < 4; j++)
                    mma_h(acc[i][j], a0, a1, a2, a3, bf[j][0], bf[j][1]);
            }
        }
        __syncthreads();
    }

    long row0 = (long)blockIdx.y * 128 + mb;
    long col0 = (long)blockIdx.x * 128 + nb;
    #pragma unroll
    for (int i = 0; i < 4; i++) {
        #pragma unroll
        for (int j = 0; j < 4; j++) {
            long gcol = col0 + j * 8 + 2 * c;
            #pragma unroll
            for (int half_ = 0; half_ < 2; half_++) {
                long grow = row0 + i * 16 + r + half_ * 8;
                float vx = acc[i][j][half_ * 2 + 0];
                float vy = acc[i][j][half_ * 2 + 1];
                if (bias) { vx += bias[gcol]; vy += bias[gcol + 1]; }
                if (GELU_) {
                    vx = 0.5f * vx * (1.f + erff(vx * 0.70710678118654752f));
                    vy = 0.5f * vy * (1.f + erff(vy * 0.70710678118654752f));
                }
                if (resid) {
                    const float2 rr = *reinterpret_cast<const float2*>(resid + grow * ldr + gcol);
                    vx += rr.x; vy += rr.y;
                }
                if (HOUT) {
                    *reinterpret_cast<__half2*>((__half*)Cv + grow * ldc + gcol) =
                        __floats2half2_rn(vx, vy);
                } else {
                    float2 o; o.x = vx; o.y = vy;
                    *reinterpret_cast<float2*>((float*)Cv + grow * ldc + gcol) = o;
                }
            }
        }
    }
}

// ---------------- flash attention (fp16 operands, fp32 softmax/accum) ----------------
#define QS 72
#define KS 72
#define VS 72
#define PS 72
#define FLASH_SMEM ((128*QS + 2*64*KS + 2*64*VS + 128*PS) * 2)

__global__ void __launch_bounds__(256) flash_kernel(const __half* __restrict__ qkv,
                                                    __half* __restrict__ y) {
    extern __shared__ __half fsh[];
    __half* Qs = fsh;                     // 128 x QS
    __half* Ks = Qs + 128 * QS;           // 2 x 64 x KS
    __half* Vs = Ks + 2 * 64 * KS;        // 2 x 64 x VS
    __half* Ps = Vs + 2 * 64 * VS;        // 128 x PS

    int tid = threadIdx.x;
    int wid = tid >> 5, lane = tid & 31;
    int r = lane >> 2, c = lane & 3;
    int mb = wid * 16;
    int l7 = lane & 7, l8 = lane & 8, lh = (lane >> 4) << 3;

    int bh = blockIdx.y;
    int b = bh >> 4, h = bh & 15;
    long qrow0 = (long)b * NN + (long)blockIdx.x * 128;
    long kvrow0 = (long)b * NN;
    const __half* qg = qkv + qrow0 * 3072 + h * 64;
    const __half* kg = qkv + kvrow0 * 3072 + 1024 + h * 64;
    const __half* vg = qkv + kvrow0 * 3072 + 2048 + h * 64;

    uint32_t qsb = smem_u32(Qs), ksb = smem_u32(Ks), vsb = smem_u32(Vs), psb = smem_u32(Ps);

    // Q load (group 0): 128 rows x 8 chunks(16B)
    #pragma unroll
    for (int t = tid; t < 1024; t += 256) {
        int row = t >> 3, ch = t & 7;
        cp16(qsb + (row * QS + ch * 8) * 2, qg + (long)row * 3072 + ch * 8);
    }
    cp_commit();

    auto load_kv = [&](int i, int s) {
        long rb = (long)i * 64;
        #pragma unroll
        for (int t = tid; t < 512; t += 256) {
            int row = t >> 3, ch = t & 7;
            cp16(ksb + ((s * 64 + row) * KS + ch * 8) * 2, kg + (rb + row) * 3072 + ch * 8);
        }
        #pragma unroll
        for (int t = tid; t < 512; t += 256) {
            int row = t >> 3, ch = t & 7;
            cp16(vsb + ((s * 64 + row) * VS + ch * 8) * 2, vg + (rb + row) * 3072 + ch * 8);
        }
        cp_commit();
    };

    load_kv(0, 0);

    float m0 = -1e30f, m1 = -1e30f, l0 = 0.f, l1 = 0.f;
    float o[8][4];
    #pragma unroll
    for (int j = 0; j < 8; j++)
        #pragma unroll
        for (int e = 0; e < 4; e++) o[j][e] = 0.f;

    const int niter = NN / 64;
    for (int it = 0; it < niter; it++) {
        int s = it & 1;
        if (it + 1 < niter) { load_kv(it + 1, s ^ 1); cp_wait1(); } else { cp_wait0(); }
        __syncthreads();

        // ---- S = Q @ K^T ----
        float sacc[8][4];
        #pragma unroll
        for (int j = 0; j < 8; j++)
            #pragma unroll
            for (int e = 0; e < 4; e++) sacc[j][e] = 0.f;

        uint32_t ks = ksb + s * 64 * KS * 2;
        #pragma unroll
        for (int kk = 0; kk < 64; kk += 16) {
            uint32_t a0, a1, a2, a3;
            ldmx4(a0, a1, a2, a3, qsb + ((mb + l7 + l8) * QS + kk + lh) * 2);
            #pragma unroll
            for (int j = 0; j < 8; j++) {
                uint32_t b0, b1;
                ldmx2(b0, b1, ks + ((j * 8 + l7) * KS + kk + l8) * 2);
                mma_h(sacc[j], a0, a1, a2, a3, b0, b1);
            }
        }

        // ---- online softmax ----
        float mx0 = -1e30f, mx1 = -1e30f;
        #pragma unroll
        for (int j = 0; j < 8; j++) {
            mx0 = fmaxf(mx0, fmaxf(sacc[j][0], sacc[j][1]));
            mx1 = fmaxf(mx1, fmaxf(sacc[j][2], sacc[j][3]));
        }
        #pragma unroll
        for (int off = 1; off <= 2; off <<= 1) {
            mx0 = fmaxf(mx0, __shfl_xor_sync(0xffffffffu, mx0, off));
            mx1 = fmaxf(mx1, __shfl_xor_sync(0xffffffffu, mx1, off));
        }
        float mn0 = fmaxf(m0, mx0), mn1 = fmaxf(m1, mx1);
        float sc0 = __expf(m0 - mn0), sc1 = __expf(m1 - mn1);
        float sum0 = 0.f, sum1 = 0.f;
        #pragma unroll
        for (int j = 0; j < 8; j++) {
            float e0 = __expf(sacc[j][0] - mn0);
            float e1 = __expf(sacc[j][1] - mn0);
            float e2 = __expf(sacc[j][2] - mn1);
            float e3 = __expf(sacc[j][3] - mn1);
            sum0 += e0 + e1; sum1 += e2 + e3;
            *reinterpret_cast<__half2*>(&Ps[(mb + r) * PS + j * 8 + 2 * c]) = __floats2half2_rn(e0, e1);
            *reinterpret_cast<__half2*>(&Ps[(mb + r + 8) * PS + j * 8 + 2 * c]) = __floats2half2_rn(e2, e3);
        }
        #pragma unroll
        for (int off = 1; off <= 2; off <<= 1) {
            sum0 += __shfl_xor_sync(0xffffffffu, sum0, off);
            sum1 += __shfl_xor_sync(0xffffffffu, sum1, off);
        }
        l0 = l0 * sc0 + sum0;
        l1 = l1 * sc1 + sum1;
        m0 = mn0; m1 = mn1;
        #pragma unroll
        for (int j = 0; j < 8; j++) {
            o[j][0] *= sc0; o[j][1] *= sc0; o[j][2] *= sc1; o[j][3] *= sc1;
        }
        __syncwarp();

        // ---- O += P @ V  (V transposed in-register via ldmatrix.trans) ----
        uint32_t vs = vsb + s * 64 * VS * 2;
        #pragma unroll
        for (int kk = 0; kk < 64; kk += 16) {
            uint32_t a0, a1, a2, a3;
            ldmx4(a0, a1, a2, a3, psb + ((mb + l7 + l8) * PS + kk + lh) * 2);
            #pragma unroll
            for (int j = 0; j < 8; j++) {
                uint32_t b0, b1;
                ldmx2t(b0, b1, vs + ((kk + l7 + l8) * VS + j * 8) * 2);
                mma_h(o[j], a0, a1, a2, a3, b0, b1);
            }
        }
        __syncwarp();
        __syncthreads();
    }

    // ---- finalize ----
    float inv0 = 1.f / l0, inv1 = 1.f / l1;
    long grow0 = qrow0 + mb + r;
    long grow1 = grow0 + 8;
    #pragma unroll
    for (int j = 0; j < 8; j++) {
        long gcol = h * 64 + j * 8 + 2 * c;
        *reinterpret_cast<__half2*>(y + grow0 * CC + gcol) =
            __floats2half2_rn(o[j][0] * inv0, o[j][1] * inv0);
        *reinterpret_cast<__half2*>(y + grow1 * CC + gcol) =
            __floats2half2_rn(o[j][2] * inv1, o[j][3] * inv1);
    }
}

// ---------------- host ----------------
template<typename T>
static T* sym_addr(const void* s) {
    void* p = nullptr;
    cudaGetSymbolAddress(&p, s);
    return (T*)p;
}

extern "C" void kernel_launch(void* const* d_in, const int* in_sizes, int n_in,
                              void* d_out, int out_size) {
    const float* x      = (const float*)d_in[0];
    const float* Wq     = (const float*)d_in[1];
    const float* Wk     = (const float*)d_in[2];
    const float* Wv     = (const float*)d_in[3];
    const float* Wp     = (const float*)d_in[4];
    const float* bp     = (const float*)d_in[5];
    const float* W1     = (const float*)d_in[6];
    const float* b1     = (const float*)d_in[7];
    const float* W2     = (const float*)d_in[8];
    const float* b2     = (const float*)d_in[9];
    const float* gamma1 = (const float*)d_in[10];
    const float* beta1  = (const float*)d_in[11];
    const float* gamma2 = (const float*)d_in[12];
    const float* beta2  = (const float*)d_in[13];
    float* out = (float*)d_out;

    __half* xn    = sym_addr<__half>(g_xn);
    __half* qkv   = sym_addr<__half>(g_qkv);
    __half* y     = sym_addr<__half>(g_y);
    float*  x2    = sym_addr<float >(g_x2);
    __half* hb    = sym_addr<__half>(g_hb);
    __half* Wqkvt = sym_addr<__half>(g_Wqkvt);
    __half* Wpt   = sym_addr<__half>(g_Wpt);
    __half* W1t   = sym_addr<__half>(g_W1t);
    __half* W2t   = sym_addr<__half>(g_W2t);

    cudaFuncSetAttribute(flash_kernel, cudaFuncAttributeMaxDynamicSharedMemorySize, FLASH_SMEM);

    dim3 tb(32, 8);

    // weight transposes fp32->fp16; q scale folded into Wq (0.125 exact)
    transpose_cvt<<<dim3(CC/32, CC/32), tb>>>(Wq, CC, Wqkvt,                   CC, 0.125f);
    transpose_cvt<<<dim3(CC/32, CC/32), tb>>>(Wk, CC, Wqkvt + (size_t)CC*CC,   CC, 1.f);
    transpose_cvt<<<dim3(CC/32, CC/32), tb>>>(Wv, CC, Wqkvt + (size_t)2*CC*CC, CC, 1.f);
    transpose_cvt<<<dim3(CC/32, CC/32), tb>>>(Wp, CC, Wpt, CC, 1.f);
    transpose_cvt<<<dim3(FF/32, CC/32), tb>>>(W1, FF, W1t, CC, 1.f);
    transpose_cvt<<<dim3(CC/32, FF/32), tb>>>(W2, CC, W2t, FF, 1.f);

    // LN1 -> fp16
    layernorm_kernel<<<RR, 256>>>(x, gamma1, beta1, xn);

    // fused QKV: [4096, 3072] fp16
    hgemm<false, true><<<dim3(3*CC/128, RR/128), 256>>>(CC,
        xn, CC, Wqkvt, CC, qkv, 3*CC, nullptr, nullptr, 0);

    // flash attention -> y fp16
    flash_kernel<<<dim3(NN/128, BB*HH), 256, FLASH_SMEM>>>(qkv, y);

    // x2 = x + y @ Wp + bp   (fp32 out)
    hgemm<false, false><<<dim3(CC/128, RR/128), 256>>>(CC,
        y, CC, Wpt, CC, x2, CC, bp, x, CC);

    // LN2 -> fp16
    layernorm_kernel<<<RR, 256>>>(x2, gamma2, beta2, xn);

    // hb = fp16(gelu(xn @ W1 + b1))
    hgemm<true, true><<<dim3(FF/128, RR/128), 256>>>(CC,
        xn, CC, W1t, CC, hb, FF, b1, nullptr, 0);

    // out = x2 + hb @ W2 + b2  (fp32 out)
    hgemm<false, false><<<dim3(CC/128, RR/128), 256>>>(FF,
        hb, FF, W2t, FF, out, CC, b2, x2, CC);
}